// round 4
// baseline (speedup 1.0000x reference)
#include <cuda_runtime.h>

#define NN 50000
#define HH 256
#define EE 320000
#define NL 5

// ---------------- scratch (static __device__, no allocation) ----------------
__device__ __align__(16) float g_h[2][NN * HH];   // ping-pong node features
__device__ __align__(16) float g_agg[NN * HH];    // per-layer aggregation
__device__ int   g_deg[NN];
__device__ int   g_cur[NN];
__device__ int   g_off[NN];
__device__ float g_dinv[NN];
__device__ int   g_src[EE];
__device__ float g_w[EE];
__device__ __align__(16) float g_s4[NN * 4];      // per-node sum of norm*edge_attr
__device__ __align__(16) float g_bnsum[NL * HH];
__device__ __align__(16) float g_bnsq[NL * HH];
__device__ int   g_is64;                          // edge_index dtype flag

// ---------------- setup kernels ----------------
__global__ void zero_kernel() {
    int i = blockIdx.x * blockDim.x + threadIdx.x;
    if (i == 0) g_is64 = 1;
    if (i < NN) { g_deg[i] = 0; g_cur[i] = 0; }
    if (i < NN * 4) g_s4[i] = 0.f;
    if (i < NL * HH) { g_bnsum[i] = 0.f; g_bnsq[i] = 0.f; }
}

// Probe dtype of edge_index (int64 vs int32) without OOB reads either way.
__global__ void detect_kernel(const unsigned long long* __restrict__ p) {
    int e = blockIdx.x * blockDim.x + threadIdx.x;
    if (e < EE) {
        if (p[e] >= (unsigned long long)NN) g_is64 = 0;
    }
}

__global__ void deg_kernel(const void* __restrict__ eiv) {
    int e = blockIdx.x * blockDim.x + threadIdx.x;
    if (e >= EE) return;
    int c;
    if (g_is64) c = (int)((const long long*)eiv)[EE + e];
    else        c = ((const int*)eiv)[EE + e];
    if (c >= 0 && c < NN) atomicAdd(&g_deg[c], 1);
}

__global__ void dinv_kernel() {
    int i = blockIdx.x * blockDim.x + threadIdx.x;
    if (i < NN) {
        int d = g_deg[i];
        g_dinv[i] = (d > 0) ? rsqrtf((float)d) : 0.f;
    }
}

// exclusive scan of g_deg -> g_off (single block, 1024 threads)
__global__ void scan_kernel() {
    __shared__ int ts[1024];
    int t = threadIdx.x;
    const int CH = (NN + 1023) / 1024;
    int beg = t * CH;
    int end = min(beg + CH, NN);
    int s = 0;
    for (int i = beg; i < end; i++) s += g_deg[i];
    ts[t] = s;
    __syncthreads();
    for (int off = 1; off < 1024; off <<= 1) {
        int v = (t >= off) ? ts[t - off] : 0;
        __syncthreads();
        ts[t] += v;
        __syncthreads();
    }
    int run = (t == 0) ? 0 : ts[t - 1];
    for (int i = beg; i < end; i++) { g_off[i] = run; run += g_deg[i]; }
}

__global__ void place_kernel(const void* __restrict__ eiv,
                             const float* __restrict__ ea) {
    int e = blockIdx.x * blockDim.x + threadIdx.x;
    if (e >= EE) return;
    int r, c;
    if (g_is64) {
        r = (int)((const long long*)eiv)[e];
        c = (int)((const long long*)eiv)[EE + e];
    } else {
        r = ((const int*)eiv)[e];
        c = ((const int*)eiv)[EE + e];
    }
    if (r < 0 || r >= NN || c < 0 || c >= NN) return;
    float w = g_dinv[r] * g_dinv[c];
    int slot = g_off[c] + atomicAdd(&g_cur[c], 1);
    g_src[slot] = r;
    g_w[slot] = w;
    atomicAdd(&g_s4[c * 4 + 0], w * ea[e * 4 + 0]);
    atomicAdd(&g_s4[c * 4 + 1], w * ea[e * 4 + 1]);
    atomicAdd(&g_s4[c * 4 + 2], w * ea[e * 4 + 2]);
    atomicAdd(&g_s4[c * 4 + 3], w * ea[e * 4 + 3]);
}

// ---------------- aggregation: one warp per node ----------------
__global__ __launch_bounds__(256) void agg_kernel(
    const float* __restrict__ xExt, int prevSel,
    const float* __restrict__ ew1l, const float* __restrict__ ew2l)
{
    int gw = (blockIdx.x * 256 + threadIdx.x) >> 5;
    int lane = threadIdx.x & 31;
    if (gw >= NN) return;
    const float* h = (prevSel == 0) ? xExt : g_h[prevSel - 1];
    const float4* h4 = (const float4*)h;

    int beg = g_off[gw];
    int cnt = g_deg[gw];
    float4 a0 = make_float4(0.f, 0.f, 0.f, 0.f);
    float4 a1 = make_float4(0.f, 0.f, 0.f, 0.f);
    for (int i = beg; i < beg + cnt; i++) {
        int src = __ldg(&g_src[i]);
        float w = __ldg(&g_w[i]);
        float4 v0 = h4[src * 64 + lane];
        float4 v1 = h4[src * 64 + 32 + lane];
        a0.x = fmaf(w, v0.x, a0.x); a0.y = fmaf(w, v0.y, a0.y);
        a0.z = fmaf(w, v0.z, a0.z); a0.w = fmaf(w, v0.w, a0.w);
        a1.x = fmaf(w, v1.x, a1.x); a1.y = fmaf(w, v1.y, a1.y);
        a1.z = fmaf(w, v1.z, a1.z); a1.w = fmaf(w, v1.w, a1.w);
    }
    // folded edge-feature term
    float s0 = g_s4[gw * 4 + 0], s1 = g_s4[gw * 4 + 1];
    float s2 = g_s4[gw * 4 + 2], s3 = g_s4[gw * 4 + 3];
    float4 e1 = ((const float4*)ew1l)[lane];
    a0.x = fmaf(s3, e1.x, a0.x); a0.y = fmaf(s3, e1.y, a0.y);
    a0.z = fmaf(s3, e1.z, a0.z); a0.w = fmaf(s3, e1.w, a0.w);
    float4 w0 = ((const float4*)(ew2l))[lane];
    float4 w1 = ((const float4*)(ew2l + 128))[lane];
    float4 w2 = ((const float4*)(ew2l + 256))[lane];
    a1.x = fmaf(s0, w0.x, fmaf(s1, w1.x, fmaf(s2, w2.x, a1.x)));
    a1.y = fmaf(s0, w0.y, fmaf(s1, w1.y, fmaf(s2, w2.y, a1.y)));
    a1.z = fmaf(s0, w0.z, fmaf(s1, w1.z, fmaf(s2, w2.z, a1.z)));
    a1.w = fmaf(s0, w0.w, fmaf(s1, w1.w, fmaf(s2, w2.w, a1.w)));

    float4* o = (float4*)g_agg;
    o[gw * 64 + lane] = a0;
    o[gw * 64 + 32 + lane] = a1;
}

// ---------------- GEMM: C = relu([h | agg] @ W + b), with BN partial stats ----
// 128x128 tile, K-chunk 8, 8x8 per thread, packed fma.rn.f32x2 (FFMA2 datapath)
__global__ __launch_bounds__(256) void gemm_kernel(
    const float* __restrict__ xExt, int prevSel, int cur,
    const float* __restrict__ W, const float* __restrict__ bias, int l)
{
    __shared__ float As[8][128];
    __shared__ float Bs[8][128];
    const float* Ah = (prevSel == 0) ? xExt : g_h[prevSel - 1];
    const float* Ag = g_agg;
    float* C = g_h[cur];

    int tid = threadIdx.x;
    int n0 = blockIdx.x * 128;
    int m0 = blockIdx.y * 128;
    int tx = tid & 15, ty = tid >> 4;
    int mSub = ty * 8, nSub = tx * 8;

    unsigned long long acc[8][4];
#pragma unroll
    for (int i = 0; i < 8; i++)
#pragma unroll
        for (int j = 0; j < 4; j++) acc[i][j] = 0ULL;

    int lm = tid >> 1;
    int lk = (tid & 1) * 4;
    int bkr = tid >> 5;
    int bn4 = (tid & 31) * 4;
    int arow = m0 + lm;

    for (int k0 = 0; k0 < 2 * HH; k0 += 8) {
        float4 av = make_float4(0.f, 0.f, 0.f, 0.f);
        if (arow < NN) {
            int k = k0 + lk;
            const float* s = (k < HH) ? (Ah + arow * HH + k)
                                      : (Ag + arow * HH + (k - HH));
            av = *(const float4*)s;
        }
        As[lk + 0][lm] = av.x;
        As[lk + 1][lm] = av.y;
        As[lk + 2][lm] = av.z;
        As[lk + 3][lm] = av.w;
        *(float4*)&Bs[bkr][bn4] = *(const float4*)(W + (k0 + bkr) * HH + n0 + bn4);
        __syncthreads();
#pragma unroll
        for (int kk = 0; kk < 8; kk++) {
            float4 a0 = *(const float4*)&As[kk][mSub];
            float4 a1 = *(const float4*)&As[kk][mSub + 4];
            const unsigned long long* bp =
                (const unsigned long long*)&Bs[kk][nSub];
            unsigned long long b0 = bp[0], b1 = bp[1], b2 = bp[2], b3 = bp[3];
            float ar[8] = {a0.x, a0.y, a0.z, a0.w, a1.x, a1.y, a1.z, a1.w};
#pragma unroll
            for (int i = 0; i < 8; i++) {
                unsigned int au = __float_as_uint(ar[i]);
                unsigned long long aa;
                asm("mov.b64 %0, {%1, %2};" : "=l"(aa) : "r"(au), "r"(au));
                asm("fma.rn.f32x2 %0, %1, %2, %0;" : "+l"(acc[i][0]) : "l"(aa), "l"(b0));
                asm("fma.rn.f32x2 %0, %1, %2, %0;" : "+l"(acc[i][1]) : "l"(aa), "l"(b1));
                asm("fma.rn.f32x2 %0, %1, %2, %0;" : "+l"(acc[i][2]) : "l"(aa), "l"(b2));
                asm("fma.rn.f32x2 %0, %1, %2, %0;" : "+l"(acc[i][3]) : "l"(aa), "l"(b3));
            }
        }
        __syncthreads();
    }

    float4 bb0 = *(const float4*)(bias + n0 + nSub);
    float4 bb1 = *(const float4*)(bias + n0 + nSub + 4);
    float br[8] = {bb0.x, bb0.y, bb0.z, bb0.w, bb1.x, bb1.y, bb1.z, bb1.w};
    float colSum[8], colSq[8];
#pragma unroll
    for (int j = 0; j < 8; j++) { colSum[j] = 0.f; colSq[j] = 0.f; }

#pragma unroll
    for (int i = 0; i < 8; i++) {
        int row = m0 + mSub + i;
        if (row < NN) {
            float o[8];
#pragma unroll
            for (int j = 0; j < 4; j++) {
                unsigned int lo, hi;
                asm("mov.b64 {%0, %1}, %2;" : "=r"(lo), "=r"(hi) : "l"(acc[i][j]));
                o[2 * j]     = __uint_as_float(lo);
                o[2 * j + 1] = __uint_as_float(hi);
            }
#pragma unroll
            for (int j = 0; j < 8; j++) {
                float v = fmaxf(o[j] + br[j], 0.f);
                o[j] = v;
                colSum[j] += v;
                colSq[j] += v * v;
            }
            *(float4*)&C[row * HH + n0 + nSub] =
                make_float4(o[0], o[1], o[2], o[3]);
            *(float4*)&C[row * HH + n0 + nSub + 4] =
                make_float4(o[4], o[5], o[6], o[7]);
        }
    }

    // block-level BN partial reduction (reuse As as 256-float scratch)
    __syncthreads();
    float* red = &As[0][0];
    red[tid] = 0.f;
    __syncthreads();
#pragma unroll
    for (int j = 0; j < 8; j++) {
        atomicAdd(&red[nSub + j], colSum[j]);
        atomicAdd(&red[128 + nSub + j], colSq[j]);
    }
    __syncthreads();
    if (tid < 128) {
        atomicAdd(&g_bnsum[l * HH + n0 + tid], red[tid]);
        atomicAdd(&g_bnsq[l * HH + n0 + tid], red[128 + tid]);
    }
}

// ---------------- BN apply (+ optional relu) ----------------
__global__ __launch_bounds__(256) void bn_kernel(
    int cur, int l, const float* __restrict__ gm, const float* __restrict__ bt,
    float* __restrict__ dout, int last)
{
    int idx = blockIdx.x * blockDim.x + threadIdx.x;
    if (idx >= NN * 64) return;
    int c4 = idx & 63;
    const float4* S = (const float4*)(g_bnsum + l * HH);
    const float4* Q = (const float4*)(g_bnsq + l * HH);
    float4 s = S[c4], q = Q[c4];
    const float invN = 1.0f / (float)NN;
    float4 mu = make_float4(s.x * invN, s.y * invN, s.z * invN, s.w * invN);
    float4 iv;
    iv.x = rsqrtf(fmaf(-mu.x, mu.x, q.x * invN) + 1e-5f);
    iv.y = rsqrtf(fmaf(-mu.y, mu.y, q.y * invN) + 1e-5f);
    iv.z = rsqrtf(fmaf(-mu.z, mu.z, q.z * invN) + 1e-5f);
    iv.w = rsqrtf(fmaf(-mu.w, mu.w, q.w * invN) + 1e-5f);
    float4 g4 = ((const float4*)gm)[c4];
    float4 b4 = ((const float4*)bt)[c4];
    float4 x = ((const float4*)g_h[cur])[idx];
    float4 y;
    y.x = fmaf((x.x - mu.x) * iv.x, g4.x, b4.x);
    y.y = fmaf((x.y - mu.y) * iv.y, g4.y, b4.y);
    y.z = fmaf((x.z - mu.z) * iv.z, g4.z, b4.z);
    y.w = fmaf((x.w - mu.w) * iv.w, g4.w, b4.w);
    if (!last) {
        y.x = fmaxf(y.x, 0.f); y.y = fmaxf(y.y, 0.f);
        y.z = fmaxf(y.z, 0.f); y.w = fmaxf(y.w, 0.f);
    }
    float4* o = last ? (float4*)dout : (float4*)g_h[cur];
    o[idx] = y;
}

// ---------------- launch ----------------
extern "C" void kernel_launch(void* const* d_in, const int* in_sizes, int n_in,
                              void* d_out, int out_size)
{
    const float* x   = (const float*)d_in[0];
    const void*  ei  = d_in[1];
    const float* ea  = (const float*)d_in[2];
    const float* mw  = (const float*)d_in[3];
    const float* mb  = (const float*)d_in[4];
    const float* ew1 = (const float*)d_in[5];
    const float* ew2 = (const float*)d_in[6];
    const float* bg  = (const float*)d_in[7];
    const float* bb  = (const float*)d_in[8];
    float* out = (float*)d_out;

    zero_kernel<<<(NN * 4 + 255) / 256, 256>>>();
    detect_kernel<<<(EE + 255) / 256, 256>>>(
        (const unsigned long long*)ei);
    deg_kernel<<<(EE + 255) / 256, 256>>>(ei);
    dinv_kernel<<<(NN + 255) / 256, 256>>>();
    scan_kernel<<<1, 1024>>>();
    place_kernel<<<(EE + 255) / 256, 256>>>(ei, ea);

    for (int l = 0; l < NL; l++) {
        int cur = l & 1;
        int prevSel = (l == 0) ? 0 : (((l - 1) & 1) + 1);
        agg_kernel<<<(NN + 7) / 8, 256>>>(x, prevSel,
                                          ew1 + l * (HH / 2),
                                          ew2 + l * 3 * (HH / 2));
        dim3 gg(2, (NN + 127) / 128);
        gemm_kernel<<<gg, 256>>>(x, prevSel, cur,
                                 mw + (size_t)l * 2 * HH * HH,
                                 mb + l * HH, l);
        bn_kernel<<<(NN * 64 + 255) / 256, 256>>>(
            cur, l, bg + l * HH, bb + l * HH, out, (l == NL - 1) ? 1 : 0);
    }
}

// round 6
// speedup vs baseline: 2.7494x; 2.7494x over previous
#include <cuda_runtime.h>
#include <cuda_bf16.h>
#include <cstdint>

#define NN 50000
#define NPAD 50048
#define HH 256
#define EE 320000
#define NL 5
#define KTOT 512
#define KC 64

// ---------------- scratch (static __device__, no allocation) ----------------
__device__ __align__(16) float g_h[2][NN * HH];   // ping-pong node features (fp32)
__device__ int   g_deg[NN];
__device__ int   g_cur[NN];
__device__ int   g_off[NN];
__device__ float g_dinv[NN];
__device__ int   g_src[EE];
__device__ float g_w[EE];
__device__ __align__(16) float g_s4[NN * 4];
__device__ __align__(16) float g_bnsum[NL * HH];
__device__ __align__(16) float g_bnsq[NL * HH];
__device__ int   g_is64;

// bf16-split A matrix [NPAD][512]: cols 0-255 = h part, 256-511 = agg part
__device__ __align__(16) __nv_bfloat16 g_abh[(size_t)NPAD * KTOT];
__device__ __align__(16) __nv_bfloat16 g_abl[(size_t)NPAD * KTOT];
// bf16-split W transposed: [NL][N=256][K=512]
__device__ __align__(16) __nv_bfloat16 g_wbh[NL * 256 * KTOT];
__device__ __align__(16) __nv_bfloat16 g_wbl[NL * 256 * KTOT];

// ---------------- helpers ----------------
__device__ __forceinline__ uint32_t smem_u32(const void* p) {
    uint32_t a;
    asm("{ .reg .u64 t; cvta.to.shared.u64 t, %1; cvt.u32.u64 %0, t; }"
        : "=r"(a) : "l"(p));
    return a;
}
__device__ __forceinline__ void cp16(uint32_t d, const void* s) {
    asm volatile("cp.async.cg.shared.global [%0], [%1], 16;"
                 :: "r"(d), "l"(s) : "memory");
}
#define CP_COMMIT() asm volatile("cp.async.commit_group;" ::: "memory")
#define CP_WAIT0()  asm volatile("cp.async.wait_group 0;" ::: "memory")
#define LDMX4(r0, r1, r2, r3, a) \
    asm volatile("ldmatrix.sync.aligned.m8n8.x4.shared.b16 {%0,%1,%2,%3}, [%4];" \
                 : "=r"(r0), "=r"(r1), "=r"(r2), "=r"(r3) : "r"(a))
#define MMA16816(d, a, b) \
    asm volatile("mma.sync.aligned.m16n8k16.row.col.f32.bf16.bf16.f32 " \
                 "{%0,%1,%2,%3},{%4,%5,%6,%7},{%8,%9},{%0,%1,%2,%3};" \
                 : "+f"((d)[0]), "+f"((d)[1]), "+f"((d)[2]), "+f"((d)[3]) \
                 : "r"((a)[0]), "r"((a)[1]), "r"((a)[2]), "r"((a)[3]), \
                   "r"((b)[0]), "r"((b)[1]))

__device__ __forceinline__ void split_store4(size_t idx, float4 v) {
    __nv_bfloat16 h0 = __float2bfloat16(v.x);
    __nv_bfloat16 h1 = __float2bfloat16(v.y);
    __nv_bfloat16 h2 = __float2bfloat16(v.z);
    __nv_bfloat16 h3 = __float2bfloat16(v.w);
    __nv_bfloat16 l0 = __float2bfloat16(v.x - __bfloat162float(h0));
    __nv_bfloat16 l1 = __float2bfloat16(v.y - __bfloat162float(h1));
    __nv_bfloat16 l2 = __float2bfloat16(v.z - __bfloat162float(h2));
    __nv_bfloat16 l3 = __float2bfloat16(v.w - __bfloat162float(h3));
    __nv_bfloat162 a; a.x = h0; a.y = h1;
    __nv_bfloat162 b; b.x = h2; b.y = h3;
    *(__nv_bfloat162*)(g_abh + idx) = a;
    *(__nv_bfloat162*)(g_abh + idx + 2) = b;
    __nv_bfloat162 c; c.x = l0; c.y = l1;
    __nv_bfloat162 d; d.x = l2; d.y = l3;
    *(__nv_bfloat162*)(g_abl + idx) = c;
    *(__nv_bfloat162*)(g_abl + idx + 2) = d;
}

// ---------------- setup kernels ----------------
__global__ void zero_kernel() {
    int i = blockIdx.x * blockDim.x + threadIdx.x;
    if (i == 0) g_is64 = 1;
    if (i < NN) { g_deg[i] = 0; g_cur[i] = 0; }
    if (i < NN * 4) g_s4[i] = 0.f;
    if (i < NL * HH) { g_bnsum[i] = 0.f; g_bnsq[i] = 0.f; }
}

__global__ void detect_kernel(const unsigned long long* __restrict__ p) {
    int e = blockIdx.x * blockDim.x + threadIdx.x;
    if (e < EE) {
        if (p[e] >= (unsigned long long)NN) g_is64 = 0;
    }
}

__global__ void deg_kernel(const void* __restrict__ eiv) {
    int e = blockIdx.x * blockDim.x + threadIdx.x;
    if (e >= EE) return;
    int c;
    if (g_is64) c = (int)((const long long*)eiv)[EE + e];
    else        c = ((const int*)eiv)[EE + e];
    if (c >= 0 && c < NN) atomicAdd(&g_deg[c], 1);
}

__global__ void dinv_kernel() {
    int i = blockIdx.x * blockDim.x + threadIdx.x;
    if (i < NN) {
        int d = g_deg[i];
        g_dinv[i] = (d > 0) ? rsqrtf((float)d) : 0.f;
    }
}

__global__ void scan_kernel() {
    __shared__ int ts[1024];
    int t = threadIdx.x;
    const int CH = (NN + 1023) / 1024;
    int beg = t * CH;
    int end = min(beg + CH, NN);
    int s = 0;
    for (int i = beg; i < end; i++) s += g_deg[i];
    ts[t] = s;
    __syncthreads();
    for (int off = 1; off < 1024; off <<= 1) {
        int v = (t >= off) ? ts[t - off] : 0;
        __syncthreads();
        ts[t] += v;
        __syncthreads();
    }
    int run = (t == 0) ? 0 : ts[t - 1];
    for (int i = beg; i < end; i++) { g_off[i] = run; run += g_deg[i]; }
}

__global__ void place_kernel(const void* __restrict__ eiv,
                             const float* __restrict__ ea) {
    int e = blockIdx.x * blockDim.x + threadIdx.x;
    if (e >= EE) return;
    int r, c;
    if (g_is64) {
        r = (int)((const long long*)eiv)[e];
        c = (int)((const long long*)eiv)[EE + e];
    } else {
        r = ((const int*)eiv)[e];
        c = ((const int*)eiv)[EE + e];
    }
    if (r < 0 || r >= NN || c < 0 || c >= NN) return;
    float w = g_dinv[r] * g_dinv[c];
    int slot = g_off[c] + atomicAdd(&g_cur[c], 1);
    g_src[slot] = r;
    g_w[slot] = w;
    atomicAdd(&g_s4[c * 4 + 0], w * ea[e * 4 + 0]);
    atomicAdd(&g_s4[c * 4 + 1], w * ea[e * 4 + 1]);
    atomicAdd(&g_s4[c * 4 + 2], w * ea[e * 4 + 2]);
    atomicAdd(&g_s4[c * 4 + 3], w * ea[e * 4 + 3]);
}

// x -> bf16 split into A cols 0-255 (first layer)
__global__ void conv_x_kernel(const float* __restrict__ x) {
    int i = blockIdx.x * blockDim.x + threadIdx.x;
    if (i >= NN * 64) return;
    int row = i >> 6;
    int col = (i & 63) * 4;
    float4 v = ((const float4*)x)[i];
    split_store4((size_t)row * KTOT + col, v);
}

// W [NL][512][256] -> transposed bf16 split [NL][256][512]
__global__ void conv_w_kernel(const float* __restrict__ mw) {
    int i = blockIdx.x * blockDim.x + threadIdx.x;
    if (i >= NL * KTOT * 256) return;
    int l = i / (KTOT * 256);
    int r = i - l * (KTOT * 256);
    int n = r & 255;
    int k = r >> 8;
    float v = mw[i];
    __nv_bfloat16 h = __float2bfloat16(v);
    __nv_bfloat16 lo = __float2bfloat16(v - __bfloat162float(h));
    size_t o = ((size_t)l * 256 + n) * KTOT + k;
    g_wbh[o] = h;
    g_wbl[o] = lo;
}

// ---------------- aggregation: one warp per node, writes bf16 split ----------
__global__ __launch_bounds__(256) void agg_kernel(
    const float* __restrict__ xExt, int prevSel,
    const float* __restrict__ ew1l, const float* __restrict__ ew2l)
{
    int gw = (blockIdx.x * 256 + threadIdx.x) >> 5;
    int lane = threadIdx.x & 31;
    if (gw >= NN) return;
    const float* h = (prevSel == 0) ? xExt : g_h[prevSel - 1];
    const float4* h4 = (const float4*)h;

    int beg = g_off[gw];
    int cnt = g_deg[gw];
    float4 a0 = make_float4(0.f, 0.f, 0.f, 0.f);
    float4 a1 = make_float4(0.f, 0.f, 0.f, 0.f);
    for (int i = beg; i < beg + cnt; i++) {
        int src = __ldg(&g_src[i]);
        float w = __ldg(&g_w[i]);
        float4 v0 = h4[src * 64 + lane];
        float4 v1 = h4[src * 64 + 32 + lane];
        a0.x = fmaf(w, v0.x, a0.x); a0.y = fmaf(w, v0.y, a0.y);
        a0.z = fmaf(w, v0.z, a0.z); a0.w = fmaf(w, v0.w, a0.w);
        a1.x = fmaf(w, v1.x, a1.x); a1.y = fmaf(w, v1.y, a1.y);
        a1.z = fmaf(w, v1.z, a1.z); a1.w = fmaf(w, v1.w, a1.w);
    }
    float s0 = g_s4[gw * 4 + 0], s1 = g_s4[gw * 4 + 1];
    float s2 = g_s4[gw * 4 + 2], s3 = g_s4[gw * 4 + 3];
    float4 e1 = ((const float4*)ew1l)[lane];
    a0.x = fmaf(s3, e1.x, a0.x); a0.y = fmaf(s3, e1.y, a0.y);
    a0.z = fmaf(s3, e1.z, a0.z); a0.w = fmaf(s3, e1.w, a0.w);
    float4 w0 = ((const float4*)(ew2l))[lane];
    float4 w1 = ((const float4*)(ew2l + 128))[lane];
    float4 w2 = ((const float4*)(ew2l + 256))[lane];
    a1.x = fmaf(s0, w0.x, fmaf(s1, w1.x, fmaf(s2, w2.x, a1.x)));
    a1.y = fmaf(s0, w0.y, fmaf(s1, w1.y, fmaf(s2, w2.y, a1.y)));
    a1.z = fmaf(s0, w0.z, fmaf(s1, w1.z, fmaf(s2, w2.z, a1.z)));
    a1.w = fmaf(s0, w0.w, fmaf(s1, w1.w, fmaf(s2, w2.w, a1.w)));

    split_store4((size_t)gw * KTOT + 256 + lane * 4, a0);
    split_store4((size_t)gw * KTOT + 256 + 128 + lane * 4, a1);
}

// ---------------- mma.sync GEMM: C = relu(A @ W^T + b) + BN partial stats ----
// CTA 128x128, 8 warps (warp tile 64x32), K=512 in 8 chunks of 64, bf16-split.
#define LDA 72                 // bf16 elems per smem row (144 B, conflict-free)
#define MATB (128 * LDA * 2)   // 18432 bytes per matrix tile
#define BUFB (4 * MATB)        // Ah, Al, Bh, Bl

__global__ __launch_bounds__(256) void gemm_mma(
    int cur, const float* __restrict__ bias, int l)
{
    extern __shared__ __align__(16) char sm[];
    __shared__ float s_red[256];
    uint32_t sbase = smem_u32(sm);
    int tid = threadIdx.x, lane = tid & 31, wid = tid >> 5;
    int n0 = blockIdx.x * 128, m0 = blockIdx.y * 128;
    int warp_m = (wid >> 2) * 64, warp_n = (wid & 3) * 32;

    const __nv_bfloat16* BhG = g_wbh + ((size_t)l * 256 + n0) * KTOT;
    const __nv_bfloat16* BlG = g_wbl + ((size_t)l * 256 + n0) * KTOT;
    float* C = g_h[cur];

    s_red[tid] = 0.f;

    float acc[4][4][4];
#pragma unroll
    for (int i = 0; i < 4; i++)
#pragma unroll
        for (int j = 0; j < 4; j++)
#pragma unroll
            for (int k = 0; k < 4; k++) acc[i][j][k] = 0.f;

    // prefetch chunk 0
    {
        int c = 0;
        uint32_t bb = sbase;
#pragma unroll
        for (int it = 0; it < 4; it++) {
            int idx = tid + it * 256;
            int r = idx >> 3, sg = idx & 7;
            uint32_t off = (uint32_t)(r * 144 + sg * 16);
            size_t ao = (size_t)(m0 + r) * KTOT + c * KC + sg * 8;
            size_t bo = (size_t)r * KTOT + c * KC + sg * 8;
            cp16(bb + off, g_abh + ao);
            cp16(bb + MATB + off, g_abl + ao);
            cp16(bb + 2 * MATB + off, BhG + bo);
            cp16(bb + 3 * MATB + off, BlG + bo);
        }
        CP_COMMIT();
    }

    for (int c = 0; c < 8; c++) {
        CP_WAIT0();
        __syncthreads();
        if (c < 7) {
            int cn = c + 1;
            uint32_t bb = sbase + (cn & 1) * BUFB;
#pragma unroll
            for (int it = 0; it < 4; it++) {
                int idx = tid + it * 256;
                int r = idx >> 3, sg = idx & 7;
                uint32_t off = (uint32_t)(r * 144 + sg * 16);
                size_t ao = (size_t)(m0 + r) * KTOT + cn * KC + sg * 8;
                size_t bo = (size_t)r * KTOT + cn * KC + sg * 8;
                cp16(bb + off, g_abh + ao);
                cp16(bb + MATB + off, g_abl + ao);
                cp16(bb + 2 * MATB + off, BhG + bo);
                cp16(bb + 3 * MATB + off, BlG + bo);
            }
            CP_COMMIT();
        }
        // compute on buffer c&1
        uint32_t base = sbase + (c & 1) * BUFB;
        int rB = warp_n + (lane & 7) + ((lane & 16) ? 8 : 0);
        int rA = warp_m + (lane & 15);
#pragma unroll
        for (int kk = 0; kk < 4; kk++) {
            int kB = kk * 16 + ((lane & 8) ? 8 : 0);
            int kA = kk * 16 + ((lane & 16) ? 8 : 0);
            uint32_t bh[4][2], bl[4][2];
#pragma unroll
            for (int ntp = 0; ntp < 2; ntp++) {
                uint32_t adr = base + 2 * MATB +
                               (uint32_t)((rB + ntp * 16) * 144 + kB * 2);
                LDMX4(bh[2 * ntp][0], bh[2 * ntp][1],
                      bh[2 * ntp + 1][0], bh[2 * ntp + 1][1], adr);
                uint32_t adr2 = adr + (uint32_t)MATB;
                LDMX4(bl[2 * ntp][0], bl[2 * ntp][1],
                      bl[2 * ntp + 1][0], bl[2 * ntp + 1][1], adr2);
            }
#pragma unroll
            for (int mt = 0; mt < 4; mt++) {
                uint32_t ah[4], al[4];
                uint32_t adr = base + (uint32_t)((rA + mt * 16) * 144 + kA * 2);
                LDMX4(ah[0], ah[1], ah[2], ah[3], adr);
                uint32_t adr2 = adr + (uint32_t)MATB;
                LDMX4(al[0], al[1], al[2], al[3], adr2);
#pragma unroll
                for (int nt = 0; nt < 4; nt++) {
                    MMA16816(acc[mt][nt], ah, bh[nt]);
                    MMA16816(acc[mt][nt], ah, bl[nt]);
                    MMA16816(acc[mt][nt], al, bh[nt]);
                }
            }
        }
    }

    // ---- epilogue: bias + relu + store + BN partial stats ----
    int tq = lane >> 2, tr = lane & 3;
#pragma unroll
    for (int nt = 0; nt < 4; nt++) {
        int cl = warp_n + nt * 8 + tr * 2;
        int colg = n0 + cl;
        float b0v = __ldg(&bias[colg]);
        float b1v = __ldg(&bias[colg + 1]);
        float s0 = 0.f, s1 = 0.f, q0 = 0.f, q1 = 0.f;
#pragma unroll
        for (int mt = 0; mt < 4; mt++) {
            int row0 = m0 + warp_m + mt * 16 + tq;
            int row1 = row0 + 8;
            float v0 = fmaxf(acc[mt][nt][0] + b0v, 0.f);
            float v1 = fmaxf(acc[mt][nt][1] + b1v, 0.f);
            float v2 = fmaxf(acc[mt][nt][2] + b0v, 0.f);
            float v3 = fmaxf(acc[mt][nt][3] + b1v, 0.f);
            if (row0 < NN) {
                *(float2*)&C[(size_t)row0 * HH + colg] = make_float2(v0, v1);
                s0 += v0; s1 += v1; q0 += v0 * v0; q1 += v1 * v1;
            }
            if (row1 < NN) {
                *(float2*)&C[(size_t)row1 * HH + colg] = make_float2(v2, v3);
                s0 += v2; s1 += v3; q0 += v2 * v2; q1 += v3 * v3;
            }
        }
        atomicAdd(&s_red[cl], s0);
        atomicAdd(&s_red[128 + cl], q0);
        atomicAdd(&s_red[cl + 1], s1);
        atomicAdd(&s_red[128 + cl + 1], q1);
    }
    __syncthreads();
    if (tid < 128) {
        atomicAdd(&g_bnsum[l * HH + n0 + tid], s_red[tid]);
        atomicAdd(&g_bnsq[l * HH + n0 + tid], s_red[128 + tid]);
    }
}

// ---------------- BN apply (+relu + bf16 split for next layer) ----------------
__global__ __launch_bounds__(256) void bn_kernel(
    int cur, int l, const float* __restrict__ gm, const float* __restrict__ bt,
    float* __restrict__ dout, int last)
{
    int idx = blockIdx.x * blockDim.x + threadIdx.x;
    if (idx >= NN * 64) return;
    int c4 = idx & 63;
    int row = idx >> 6;
    const float4* S = (const float4*)(g_bnsum + l * HH);
    const float4* Q = (const float4*)(g_bnsq + l * HH);
    float4 s = S[c4], q = Q[c4];
    const float invN = 1.0f / (float)NN;
    float4 mu = make_float4(s.x * invN, s.y * invN, s.z * invN, s.w * invN);
    float4 iv;
    iv.x = rsqrtf(fmaf(-mu.x, mu.x, q.x * invN) + 1e-5f);
    iv.y = rsqrtf(fmaf(-mu.y, mu.y, q.y * invN) + 1e-5f);
    iv.z = rsqrtf(fmaf(-mu.z, mu.z, q.z * invN) + 1e-5f);
    iv.w = rsqrtf(fmaf(-mu.w, mu.w, q.w * invN) + 1e-5f);
    float4 g4 = ((const float4*)gm)[c4];
    float4 b4 = ((const float4*)bt)[c4];
    float4 x = ((const float4*)g_h[cur])[idx];
    float4 y;
    y.x = fmaf((x.x - mu.x) * iv.x, g4.x, b4.x);
    y.y = fmaf((x.y - mu.y) * iv.y, g4.y, b4.y);
    y.z = fmaf((x.z - mu.z) * iv.z, g4.z, b4.z);
    y.w = fmaf((x.w - mu.w) * iv.w, g4.w, b4.w);
    if (last) {
        ((float4*)dout)[idx] = y;
        return;
    }
    y.x = fmaxf(y.x, 0.f); y.y = fmaxf(y.y, 0.f);
    y.z = fmaxf(y.z, 0.f); y.w = fmaxf(y.w, 0.f);
    ((float4*)g_h[cur])[idx] = y;                  // fp32 for next agg
    split_store4((size_t)row * KTOT + c4 * 4, y);  // bf16 for next gemm
}

// ---------------- launch ----------------
extern "C" void kernel_launch(void* const* d_in, const int* in_sizes, int n_in,
                              void* d_out, int out_size)
{
    const float* x   = (const float*)d_in[0];
    const void*  ei  = d_in[1];
    const float* ea  = (const float*)d_in[2];
    const float* mw  = (const float*)d_in[3];
    const float* mb  = (const float*)d_in[4];
    const float* ew1 = (const float*)d_in[5];
    const float* ew2 = (const float*)d_in[6];
    const float* bg  = (const float*)d_in[7];
    const float* bb  = (const float*)d_in[8];
    float* out = (float*)d_out;

    static int smem_set = 0;
    if (!smem_set) {
        cudaFuncSetAttribute(gemm_mma, cudaFuncAttributeMaxDynamicSharedMemorySize,
                             2 * BUFB);
        smem_set = 1;
    }

    zero_kernel<<<(NN * 4 + 255) / 256, 256>>>();
    detect_kernel<<<(EE + 255) / 256, 256>>>((const unsigned long long*)ei);
    deg_kernel<<<(EE + 255) / 256, 256>>>(ei);
    dinv_kernel<<<(NN + 255) / 256, 256>>>();
    scan_kernel<<<1, 1024>>>();
    place_kernel<<<(EE + 255) / 256, 256>>>(ei, ea);
    conv_x_kernel<<<(NN * 64 + 255) / 256, 256>>>(x);
    conv_w_kernel<<<(NL * KTOT * 256 + 255) / 256, 256>>>(mw);

    for (int l = 0; l < NL; l++) {
        int cur = l & 1;
        int prevSel = (l == 0) ? 0 : (((l - 1) & 1) + 1);
        agg_kernel<<<(NN + 7) / 8, 256>>>(x, prevSel,
                                          ew1 + l * (HH / 2),
                                          ew2 + l * 3 * (HH / 2));
        dim3 gg(2, (NPAD + 127) / 128);
        gemm_mma<<<gg, 256, 2 * BUFB>>>(cur, mb + l * HH, l);
        bn_kernel<<<(NN * 64 + 255) / 256, 256>>>(
            cur, l, bg + l * HH, bb + l * HH, out, (l == NL - 1) ? 1 : 0);
    }
}

// round 11
// speedup vs baseline: 2.7827x; 1.0121x over previous
#include <cuda_runtime.h>
#include <cuda_bf16.h>
#include <cstdint>

#define NN 50000
#define NPAD 50048
#define HH 256
#define EE 320000
#define NL 5
#define KTOT 512
#define KC 64

// ---------------- scratch (static __device__, no allocation) ----------------
__device__ __align__(16) float g_h[2][NN * HH];   // ping-pong node features (fp32)
__device__ int   g_deg[NN];
__device__ int   g_cur[NN];
__device__ int   g_off[NN];
__device__ float g_dinv[NN];
__device__ int   g_src[EE];
__device__ float g_w[EE];
__device__ __align__(16) float g_s4[NN * 4];
__device__ __align__(16) float g_bnsum[NL * HH];
__device__ __align__(16) float g_bnsq[NL * HH];
__device__ int   g_is64;

// bf16-split A matrix [NPAD][512]: cols 0-255 = h part, 256-511 = agg part
// (rows >= NN stay zero: BSS-initialized, never written)
__device__ __align__(16) __nv_bfloat16 g_abh[(size_t)NPAD * KTOT];
__device__ __align__(16) __nv_bfloat16 g_abl[(size_t)NPAD * KTOT];
// bf16-split W transposed: [NL][N=256][K=512]
__device__ __align__(16) __nv_bfloat16 g_wbh[NL * 256 * KTOT];
__device__ __align__(16) __nv_bfloat16 g_wbl[NL * 256 * KTOT];

// ---------------- helpers ----------------
__device__ __forceinline__ uint32_t smem_u32(const void* p) {
    uint32_t a;
    asm("{ .reg .u64 t; cvta.to.shared.u64 t, %1; cvt.u32.u64 %0, t; }"
        : "=r"(a) : "l"(p));
    return a;
}
__device__ __forceinline__ void cp16(uint32_t d, const void* s) {
    asm volatile("cp.async.cg.shared.global [%0], [%1], 16;"
                 :: "r"(d), "l"(s) : "memory");
}
#define CP_COMMIT() asm volatile("cp.async.commit_group;" ::: "memory")
#define CP_WAIT0()  asm volatile("cp.async.wait_group 0;" ::: "memory")
#define LDMX4(r0, r1, r2, r3, a) \
    asm volatile("ldmatrix.sync.aligned.m8n8.x4.shared.b16 {%0,%1,%2,%3}, [%4];" \
                 : "=r"(r0), "=r"(r1), "=r"(r2), "=r"(r3) : "r"(a))
#define MMA16816(d, a, b) \
    asm volatile("mma.sync.aligned.m16n8k16.row.col.f32.bf16.bf16.f32 " \
                 "{%0,%1,%2,%3},{%4,%5,%6,%7},{%8,%9},{%0,%1,%2,%3};" \
                 : "+f"((d)[0]), "+f"((d)[1]), "+f"((d)[2]), "+f"((d)[3]) \
                 : "r"((a)[0]), "r"((a)[1]), "r"((a)[2]), "r"((a)[3]), \
                   "r"((b)[0]), "r"((b)[1]))

__device__ __forceinline__ void split_store4(size_t idx, float4 v) {
    __nv_bfloat16 h0 = __float2bfloat16(v.x);
    __nv_bfloat16 h1 = __float2bfloat16(v.y);
    __nv_bfloat16 h2 = __float2bfloat16(v.z);
    __nv_bfloat16 h3 = __float2bfloat16(v.w);
    __nv_bfloat16 l0 = __float2bfloat16(v.x - __bfloat162float(h0));
    __nv_bfloat16 l1 = __float2bfloat16(v.y - __bfloat162float(h1));
    __nv_bfloat16 l2 = __float2bfloat16(v.z - __bfloat162float(h2));
    __nv_bfloat16 l3 = __float2bfloat16(v.w - __bfloat162float(h3));
    __nv_bfloat162 a; a.x = h0; a.y = h1;
    __nv_bfloat162 b; b.x = h2; b.y = h3;
    *(__nv_bfloat162*)(g_abh + idx) = a;
    *(__nv_bfloat162*)(g_abh + idx + 2) = b;
    __nv_bfloat162 c; c.x = l0; c.y = l1;
    __nv_bfloat162 d; d.x = l2; d.y = l3;
    *(__nv_bfloat162*)(g_abl + idx) = c;
    *(__nv_bfloat162*)(g_abl + idx + 2) = d;
}

// ---------------- setup kernels ----------------
__global__ void zero_kernel() {
    int i = blockIdx.x * blockDim.x + threadIdx.x;
    if (i == 0) g_is64 = 1;
    if (i < NN) { g_deg[i] = 0; g_cur[i] = 0; }
    if (i < NN * 4) g_s4[i] = 0.f;
    if (i < NL * HH) { g_bnsum[i] = 0.f; g_bnsq[i] = 0.f; }
}

__global__ void detect_kernel(const unsigned long long* __restrict__ p) {
    int e = blockIdx.x * blockDim.x + threadIdx.x;
    if (e < EE) {
        if (p[e] >= (unsigned long long)NN) g_is64 = 0;
    }
}

__global__ void deg_kernel(const void* __restrict__ eiv) {
    int e = blockIdx.x * blockDim.x + threadIdx.x;
    if (e >= EE) return;
    int c;
    if (g_is64) c = (int)((const long long*)eiv)[EE + e];
    else        c = ((const int*)eiv)[EE + e];
    if (c >= 0 && c < NN) atomicAdd(&g_deg[c], 1);
}

__global__ void dinv_kernel() {
    int i = blockIdx.x * blockDim.x + threadIdx.x;
    if (i < NN) {
        int d = g_deg[i];
        g_dinv[i] = (d > 0) ? rsqrtf((float)d) : 0.f;
    }
}

__global__ void scan_kernel() {
    __shared__ int ts[1024];
    int t = threadIdx.x;
    const int CH = (NN + 1023) / 1024;
    int beg = t * CH;
    int end = min(beg + CH, NN);
    int s = 0;
    for (int i = beg; i < end; i++) s += g_deg[i];
    ts[t] = s;
    __syncthreads();
    for (int off = 1; off < 1024; off <<= 1) {
        int v = (t >= off) ? ts[t - off] : 0;
        __syncthreads();
        ts[t] += v;
        __syncthreads();
    }
    int run = (t == 0) ? 0 : ts[t - 1];
    for (int i = beg; i < end; i++) { g_off[i] = run; run += g_deg[i]; }
}

__global__ void place_kernel(const void* __restrict__ eiv,
                             const float* __restrict__ ea) {
    int e = blockIdx.x * blockDim.x + threadIdx.x;
    if (e >= EE) return;
    int r, c;
    if (g_is64) {
        r = (int)((const long long*)eiv)[e];
        c = (int)((const long long*)eiv)[EE + e];
    } else {
        r = ((const int*)eiv)[e];
        c = ((const int*)eiv)[EE + e];
    }
    if (r < 0 || r >= NN || c < 0 || c >= NN) return;
    float w = g_dinv[r] * g_dinv[c];
    int slot = g_off[c] + atomicAdd(&g_cur[c], 1);
    g_src[slot] = r;
    g_w[slot] = w;
    atomicAdd(&g_s4[c * 4 + 0], w * ea[e * 4 + 0]);
    atomicAdd(&g_s4[c * 4 + 1], w * ea[e * 4 + 1]);
    atomicAdd(&g_s4[c * 4 + 2], w * ea[e * 4 + 2]);
    atomicAdd(&g_s4[c * 4 + 3], w * ea[e * 4 + 3]);
}

// x -> bf16 split into A cols 0-255 (first layer)
__global__ void conv_x_kernel(const float* __restrict__ x) {
    int i = blockIdx.x * blockDim.x + threadIdx.x;
    if (i >= NN * 64) return;
    int row = i >> 6;
    int col = (i & 63) * 4;
    float4 v = ((const float4*)x)[i];
    split_store4((size_t)row * KTOT + col, v);
}

// W [NL][512][256] -> transposed bf16 split [NL][256][512]
__global__ void conv_w_kernel(const float* __restrict__ mw) {
    int i = blockIdx.x * blockDim.x + threadIdx.x;
    if (i >= NL * KTOT * 256) return;
    int l = i / (KTOT * 256);
    int r = i - l * (KTOT * 256);
    int n = r & 255;
    int k = r >> 8;
    float v = mw[i];
    __nv_bfloat16 h = __float2bfloat16(v);
    __nv_bfloat16 lo = __float2bfloat16(v - __bfloat162float(h));
    size_t o = ((size_t)l * 256 + n) * KTOT + k;
    g_wbh[o] = h;
    g_wbl[o] = lo;
}

// ---------------- aggregation: one warp per node, writes bf16 split ----------
__global__ __launch_bounds__(256) void agg_kernel(
    const float* __restrict__ xExt, int prevSel,
    const float* __restrict__ ew1l, const float* __restrict__ ew2l)
{
    int gw = (blockIdx.x * 256 + threadIdx.x) >> 5;
    int lane = threadIdx.x & 31;
    if (gw >= NN) return;
    const float* h = (prevSel == 0) ? xExt : g_h[prevSel - 1];
    const float4* h4 = (const float4*)h;

    int beg = g_off[gw];
    int cnt = g_deg[gw];
    float4 a0 = make_float4(0.f, 0.f, 0.f, 0.f);
    float4 a1 = make_float4(0.f, 0.f, 0.f, 0.f);
    for (int i = beg; i < beg + cnt; i++) {
        int src = __ldg(&g_src[i]);
        float w = __ldg(&g_w[i]);
        float4 v0 = h4[src * 64 + lane];
        float4 v1 = h4[src * 64 + 32 + lane];
        a0.x = fmaf(w, v0.x, a0.x); a0.y = fmaf(w, v0.y, a0.y);
        a0.z = fmaf(w, v0.z, a0.z); a0.w = fmaf(w, v0.w, a0.w);
        a1.x = fmaf(w, v1.x, a1.x); a1.y = fmaf(w, v1.y, a1.y);
        a1.z = fmaf(w, v1.z, a1.z); a1.w = fmaf(w, v1.w, a1.w);
    }
    float s0 = g_s4[gw * 4 + 0], s1 = g_s4[gw * 4 + 1];
    float s2 = g_s4[gw * 4 + 2], s3 = g_s4[gw * 4 + 3];
    float4 e1 = ((const float4*)ew1l)[lane];
    a0.x = fmaf(s3, e1.x, a0.x); a0.y = fmaf(s3, e1.y, a0.y);
    a0.z = fmaf(s3, e1.z, a0.z); a0.w = fmaf(s3, e1.w, a0.w);
    float4 w0 = ((const float4*)(ew2l))[lane];
    float4 w1 = ((const float4*)(ew2l + 128))[lane];
    float4 w2 = ((const float4*)(ew2l + 256))[lane];
    a1.x = fmaf(s0, w0.x, fmaf(s1, w1.x, fmaf(s2, w2.x, a1.x)));
    a1.y = fmaf(s0, w0.y, fmaf(s1, w1.y, fmaf(s2, w2.y, a1.y)));
    a1.z = fmaf(s0, w0.z, fmaf(s1, w1.z, fmaf(s2, w2.z, a1.z)));
    a1.w = fmaf(s0, w0.w, fmaf(s1, w1.w, fmaf(s2, w2.w, a1.w)));

    split_store4((size_t)gw * KTOT + 256 + lane * 4, a0);
    split_store4((size_t)gw * KTOT + 256 + 128 + lane * 4, a1);
}

// ---------------- mma.sync GEMM: C = relu(A @ W^T + b) + BN partial stats ----
// CTA 128x256 (full N), 8 warps as 2x4 (warp tile 64x64), K=512 in 8 chunks.
#define LDAB 144                 // smem bytes per 64-bf16 row (conflict-free)
#define MATA (128 * LDAB)        // 18432 B per A plane
#define MATBB (256 * LDAB)       // 36864 B per B plane
#define OFF_AL MATA
#define OFF_BH (2 * MATA)
#define OFF_BL (2 * MATA + MATBB)
#define BUFB (2 * MATA + 2 * MATBB)   // 110592 B per buffer

__global__ __launch_bounds__(256, 1) void gemm_mma(
    int cur, const float* __restrict__ bias, int l)
{
    extern __shared__ __align__(16) char sm[];
    __shared__ float s_red[512];
    uint32_t sbase = smem_u32(sm);
    int tid = threadIdx.x, lane = tid & 31, wid = tid >> 5;
    int m0 = blockIdx.x * 128;
    int warp_m = (wid & 1) * 64, warp_n = (wid >> 1) * 64;

    const __nv_bfloat16* BhG = g_wbh + (size_t)l * 256 * KTOT;
    const __nv_bfloat16* BlG = g_wbl + (size_t)l * 256 * KTOT;
    float* C = g_h[cur];

    s_red[tid] = 0.f;
    s_red[256 + tid] = 0.f;

    float acc[4][8][4];
#pragma unroll
    for (int i = 0; i < 4; i++)
#pragma unroll
        for (int j = 0; j < 8; j++)
#pragma unroll
            for (int k = 0; k < 4; k++) acc[i][j][k] = 0.f;

    // prefetch chunk 0
    {
        uint32_t bb = sbase;
        // A planes: 1024 segs each (128 rows x 8 x 16B)
#pragma unroll
        for (int it = 0; it < 4; it++) {
            int idx = tid + it * 256;
            int r = idx >> 3, sg = idx & 7;
            uint32_t off = (uint32_t)(r * LDAB + sg * 16);
            size_t ao = (size_t)(m0 + r) * KTOT + sg * 8;
            cp16(bb + off, g_abh + ao);
            cp16(bb + OFF_AL + off, g_abl + ao);
        }
        // B planes: 2048 segs each (256 rows x 8 x 16B)
#pragma unroll
        for (int it = 0; it < 8; it++) {
            int idx = tid + it * 256;
            int r = idx >> 3, sg = idx & 7;
            uint32_t off = (uint32_t)(r * LDAB + sg * 16);
            size_t bo = (size_t)r * KTOT + sg * 8;
            cp16(bb + OFF_BH + off, BhG + bo);
            cp16(bb + OFF_BL + off, BlG + bo);
        }
        CP_COMMIT();
    }

    for (int c = 0; c < 8; c++) {
        CP_WAIT0();
        __syncthreads();
        if (c < 7) {
            int cn = c + 1;
            uint32_t bb = sbase + (cn & 1) * BUFB;
#pragma unroll
            for (int it = 0; it < 4; it++) {
                int idx = tid + it * 256;
                int r = idx >> 3, sg = idx & 7;
                uint32_t off = (uint32_t)(r * LDAB + sg * 16);
                size_t ao = (size_t)(m0 + r) * KTOT + cn * KC + sg * 8;
                cp16(bb + off, g_abh + ao);
                cp16(bb + OFF_AL + off, g_abl + ao);
            }
#pragma unroll
            for (int it = 0; it < 8; it++) {
                int idx = tid + it * 256;
                int r = idx >> 3, sg = idx & 7;
                uint32_t off = (uint32_t)(r * LDAB + sg * 16);
                size_t bo = (size_t)r * KTOT + cn * KC + sg * 8;
                cp16(bb + OFF_BH + off, BhG + bo);
                cp16(bb + OFF_BL + off, BlG + bo);
            }
            CP_COMMIT();
        }
        // compute on buffer c&1
        uint32_t base = sbase + (c & 1) * BUFB;
        int rB = warp_n + (lane & 7) + ((lane & 16) ? 8 : 0);
        int rA = warp_m + (lane & 15);
#pragma unroll
        for (int kk = 0; kk < 4; kk++) {
            int kB = (kk * 16 + ((lane & 8) ? 8 : 0)) * 2;
            int kA = (kk * 16 + ((lane & 16) ? 8 : 0)) * 2;
            uint32_t bh[8][2], bl[8][2];
#pragma unroll
            for (int ntp = 0; ntp < 4; ntp++) {
                uint32_t adr = base + OFF_BH +
                               (uint32_t)((rB + ntp * 16) * LDAB + kB);
                LDMX4(bh[2 * ntp][0], bh[2 * ntp][1],
                      bh[2 * ntp + 1][0], bh[2 * ntp + 1][1], adr);
                uint32_t adr2 = adr + (uint32_t)(OFF_BL - OFF_BH);
                LDMX4(bl[2 * ntp][0], bl[2 * ntp][1],
                      bl[2 * ntp + 1][0], bl[2 * ntp + 1][1], adr2);
            }
#pragma unroll
            for (int mt = 0; mt < 4; mt++) {
                uint32_t ah[4], al[4];
                uint32_t adr = base + (uint32_t)((rA + mt * 16) * LDAB + kA);
                LDMX4(ah[0], ah[1], ah[2], ah[3], adr);
                uint32_t adr2 = adr + (uint32_t)OFF_AL;
                LDMX4(al[0], al[1], al[2], al[3], adr2);
#pragma unroll
                for (int nt = 0; nt < 8; nt++) {
                    MMA16816(acc[mt][nt], ah, bh[nt]);
                    MMA16816(acc[mt][nt], ah, bl[nt]);
                    MMA16816(acc[mt][nt], al, bh[nt]);
                }
            }
        }
        __syncthreads();
    }

    // ---- epilogue: bias + relu + store + BN partial stats ----
    int tq = lane >> 2, tr = lane & 3;
#pragma unroll
    for (int nt = 0; nt < 8; nt++) {
        int cl = warp_n + nt * 8 + tr * 2;
        float b0v = __ldg(&bias[cl]);
        float b1v = __ldg(&bias[cl + 1]);
        float s0 = 0.f, s1 = 0.f, q0 = 0.f, q1 = 0.f;
#pragma unroll
        for (int mt = 0; mt < 4; mt++) {
            int row0 = m0 + warp_m + mt * 16 + tq;
            int row1 = row0 + 8;
            float v0 = fmaxf(acc[mt][nt][0] + b0v, 0.f);
            float v1 = fmaxf(acc[mt][nt][1] + b1v, 0.f);
            float v2 = fmaxf(acc[mt][nt][2] + b0v, 0.f);
            float v3 = fmaxf(acc[mt][nt][3] + b1v, 0.f);
            if (row0 < NN) {
                *(float2*)&C[(size_t)row0 * HH + cl] = make_float2(v0, v1);
                s0 += v0; s1 += v1; q0 += v0 * v0; q1 += v1 * v1;
            }
            if (row1 < NN) {
                *(float2*)&C[(size_t)row1 * HH + cl] = make_float2(v2, v3);
                s0 += v2; s1 += v3; q0 += v2 * v2; q1 += v3 * v3;
            }
        }
        atomicAdd(&s_red[cl], s0);
        atomicAdd(&s_red[256 + cl], q0);
        atomicAdd(&s_red[cl + 1], s1);
        atomicAdd(&s_red[256 + cl + 1], q1);
    }
    __syncthreads();
    atomicAdd(&g_bnsum[l * HH + tid], s_red[tid]);
    atomicAdd(&g_bnsq[l * HH + tid], s_red[256 + tid]);
}

// ---------------- BN apply (+relu + bf16 split for next layer) ----------------
__global__ __launch_bounds__(256) void bn_kernel(
    int cur, int l, const float* __restrict__ gm, const float* __restrict__ bt,
    float* __restrict__ dout, int last)
{
    int idx = blockIdx.x * blockDim.x + threadIdx.x;
    if (idx >= NN * 64) return;
    int c4 = idx & 63;
    int row = idx >> 6;
    const float4* S = (const float4*)(g_bnsum + l * HH);
    const float4* Q = (const float4*)(g_bnsq + l * HH);
    float4 s = S[c4], q = Q[c4];
    const float invN = 1.0f / (float)NN;
    float4 mu = make_float4(s.x * invN, s.y * invN, s.z * invN, s.w * invN);
    float4 iv;
    iv.x = rsqrtf(fmaf(-mu.x, mu.x, q.x * invN) + 1e-5f);
    iv.y = rsqrtf(fmaf(-mu.y, mu.y, q.y * invN) + 1e-5f);
    iv.z = rsqrtf(fmaf(-mu.z, mu.z, q.z * invN) + 1e-5f);
    iv.w = rsqrtf(fmaf(-mu.w, mu.w, q.w * invN) + 1e-5f);
    float4 g4 = ((const float4*)gm)[c4];
    float4 b4 = ((const float4*)bt)[c4];
    float4 x = ((const float4*)g_h[cur])[idx];
    float4 y;
    y.x = fmaf((x.x - mu.x) * iv.x, g4.x, b4.x);
    y.y = fmaf((x.y - mu.y) * iv.y, g4.y, b4.y);
    y.z = fmaf((x.z - mu.z) * iv.z, g4.z, b4.z);
    y.w = fmaf((x.w - mu.w) * iv.w, g4.w, b4.w);
    if (last) {
        ((float4*)dout)[idx] = y;
        return;
    }
    y.x = fmaxf(y.x, 0.f); y.y = fmaxf(y.y, 0.f);
    y.z = fmaxf(y.z, 0.f); y.w = fmaxf(y.w, 0.f);
    ((float4*)g_h[cur])[idx] = y;                  // fp32 for next agg
    split_store4((size_t)row * KTOT + c4 * 4, y);  // bf16 for next gemm
}

// ---------------- launch ----------------
extern "C" void kernel_launch(void* const* d_in, const int* in_sizes, int n_in,
                              void* d_out, int out_size)
{
    const float* x   = (const float*)d_in[0];
    const void*  ei  = d_in[1];
    const float* ea  = (const float*)d_in[2];
    const float* mw  = (const float*)d_in[3];
    const float* mb  = (const float*)d_in[4];
    const float* ew1 = (const float*)d_in[5];
    const float* ew2 = (const float*)d_in[6];
    const float* bg  = (const float*)d_in[7];
    const float* bb  = (const float*)d_in[8];
    float* out = (float*)d_out;

    static int smem_set = 0;
    if (!smem_set) {
        cudaFuncSetAttribute(gemm_mma, cudaFuncAttributeMaxDynamicSharedMemorySize,
                             2 * BUFB);
        smem_set = 1;
    }

    zero_kernel<<<(NN * 4 + 255) / 256, 256>>>();
    detect_kernel<<<(EE + 255) / 256, 256>>>((const unsigned long long*)ei);
    deg_kernel<<<(EE + 255) / 256, 256>>>(ei);
    dinv_kernel<<<(NN + 255) / 256, 256>>>();
    scan_kernel<<<1, 1024>>>();
    place_kernel<<<(EE + 255) / 256, 256>>>(ei, ea);
    conv_x_kernel<<<(NN * 64 + 255) / 256, 256>>>(x);
    conv_w_kernel<<<(NL * KTOT * 256 + 255) / 256, 256>>>(mw);

    for (int l = 0; l < NL; l++) {
        int cur = l & 1;
        int prevSel = (l == 0) ? 0 : (((l - 1) & 1) + 1);
        agg_kernel<<<(NN + 7) / 8, 256>>>(x, prevSel,
                                          ew1 + l * (HH / 2),
                                          ew2 + l * 3 * (HH / 2));
        gemm_mma<<<NPAD / 128, 256, 2 * BUFB>>>(cur, mb + l * HH, l);
        bn_kernel<<<(NN * 64 + 255) / 256, 256>>>(
            cur, l, bg + l * HH, bb + l * HH, out, (l == NL - 1) ? 1 : 0);
    }
}